// round 16
// baseline (speedup 1.0000x reference)
#include <cuda_runtime.h>
#include <cuda_fp16.h>

// SConv R15: R14 pipeline + smem-transpose epilogues (fully coalesced stores).
// CTA: 256 thr (8 warps 4Mx2N, warp 32x64), tile 128oc x 128px, 2 CTAs/SM.

#define B_  16
#define C1  128
#define C2  256
#define H_  128
#define W_  128
#define HW  (H_*W_)
#define EPSBN 1e-5f

typedef unsigned int uint;

__device__ __half g_xs[(size_t)3 * B_ * 130 * 4 * 4096];
__device__ __half g_ys[(size_t)B_ * 128 * 8 * 4096];
__device__ __half g_yi [(size_t)B_ * C2 * HW];
__device__ __half g_wA16[36 * 2 * 4096];
__device__ __half g_wB16[ 8 * 2 * 4096];

__device__ __forceinline__ float silu_f(float v) { return v / (1.0f + __expf(-v)); }
__device__ __forceinline__ uint smem_u32(const void* p) {
    uint a;
    asm("{ .reg .u64 t; cvta.to.shared.u64 t, %1; cvt.u32.u64 %0, t; }" : "=r"(a) : "l"(p));
    return a;
}

#define MMA16(d, a, b0v, b1v) \
    asm volatile("mma.sync.aligned.m16n8k16.row.col.f32.f16.f16.f32 " \
        "{%0,%1,%2,%3}, {%4,%5,%6,%7}, {%8,%9}, {%0,%1,%2,%3};" \
        : "+f"((d)[0]), "+f"((d)[1]), "+f"((d)[2]), "+f"((d)[3]) \
        : "r"((a).x), "r"((a).y), "r"((a).z), "r"((a).w), "r"(b0v), "r"(b1v))

#define MBAR_INIT(a, c) \
    asm volatile("mbarrier.init.shared.b64 [%0], %1;" :: "r"(a), "r"(c) : "memory")
#define MBAR_EXPECT(a, by) \
    asm volatile("mbarrier.arrive.expect_tx.shared.b64 _, [%0], %1;" :: "r"(a), "r"(by) : "memory")
#define MBAR_ARRIVE(a) \
    asm volatile("mbarrier.arrive.shared.b64 _, [%0];" :: "r"(a) : "memory")
#define BULK_G2S(dst, src, sz, mb) \
    asm volatile("cp.async.bulk.shared::cta.global.mbarrier::complete_tx::bytes [%0], [%1], %2, [%3];" \
        :: "r"(dst), "l"(src), "r"(sz), "r"(mb) : "memory")
__device__ __forceinline__ void mbar_wait(uint a, uint ph) {
    asm volatile(
        "{\n\t.reg .pred P;\n\tWL%=:\n\t"
        "mbarrier.try_wait.parity.shared.b64 P, [%0], %1;\n\t"
        "@!P bra WL%=;\n\t}" :: "r"(a), "r"(ph) : "memory");
}

#define A_BYTES 8192
#define B_BYTES 8192
#define STAGE   (A_BYTES + B_BYTES)
#define NSTG    4
#define DSMEM_BYTES 69632          // 64KB pipeline, 68KB epilogue tiles
#define NTHR 256

// epilogue smem rows: half tiles 272B/row (136 halfs), float tile 544B/row
#define YROW 272
#define ZROW 544

__device__ __forceinline__ int ysoff(int kk, int wp) {
    return kk * 256 + ((((wp >> 3) ^ (kk & 7))) << 4) + (wp & 7) * 2;
}

// --------------------------------------------------------- prep kernels ----
__device__ __forceinline__ int fragoff(int m, int kk) {
    return (((kk >> 4) * 8 + (m >> 4)) * 32 + (((m & 7) << 2) | ((kk >> 1) & 3))) * 8
         + (((kk >> 3) & 1) * 2 + ((m >> 3) & 1)) * 2 + (kk & 1);
}
__global__ __launch_bounds__(256) void k_repack(const float* __restrict__ wc,
                                                const float* __restrict__ w1) {
    int idx = blockIdx.x * 256 + threadIdx.x;
    if (idx < C2 * C1 * 9) {
        int tap = idx % 9, rest = idx / 9;
        int ic = rest % C1, oc = rest / C1;
        int it = (ic >> 5) * 9 + tap;
        g_wA16[(size_t)(it * 2 + (oc >> 7)) * 4096 + fragoff(oc & 127, ic & 31)] =
            __float2half_rn(wc[idx]);
    } else {
        int j = idx - C2 * C1 * 9;
        if (j >= C2 * C2) return;
        int ic = j % C2, oc = j / C2;
        g_wB16[(size_t)((ic >> 5) * 2 + (oc >> 7)) * 4096 + fragoff(oc & 127, ic & 31)] =
            __float2half_rn(w1[j]);
    }
}

__global__ __launch_bounds__(256) void k_prep_x(const float* __restrict__ x) {
    const int h = blockIdx.x, b = blockIdx.y;
    const int tid = threadIdx.x;
#pragma unroll
    for (int i = 0; i < 8; ++i) {
        int item = tid + i * 256;
        int kc = item >> 9, r = item & 511;
        int kk = r >> 4, g = r & 15;
        const float* src = x + (((size_t)(b * C1 + kc * 32 + kk)) * H_ + h) * W_;
        int w0 = g * 8;
        float v[10];
#pragma unroll
        for (int j = 0; j < 10; ++j) {
            int gw = w0 - 1 + j;
            v[j] = ((uint)gw < 128u) ? __ldg(src + gw) : 0.f;
        }
        uint off = (uint)(kk * 256 + ((g ^ (kk & 7)) << 4));
#pragma unroll
        for (int kx = 0; kx < 3; ++kx) {
            __align__(16) __half hh[8];
#pragma unroll
            for (int j = 0; j < 8; ++j) hh[j] = __float2half_rn(v[j + kx]);
            size_t blk = ((size_t)(kx * B_ + b) * 130 + (h + 1)) * 4 + kc;
            *(uint4*)((char*)g_xs + blk * 8192 + off) = *(const uint4*)hh;
        }
    }
}

#define Z_S0 196608
#define Z_S1 32768
#define Z_S2 262144
__global__ __launch_bounds__(256) void k_zero() {
    int idx = blockIdx.x * 256 + threadIdx.x;
    if (idx < Z_S0) {
        int i512 = idx >> 9, j = idx & 511;
        int kx = i512 % 3, rest = i512 / 3;
        int b = rest % 16; rest /= 16;
        int e = rest % 2, kc = rest / 2;
        size_t blk = ((size_t)(kx * B_ + b) * 130 + (e ? 129 : 0)) * 4 + kc;
        ((uint4*)((char*)g_xs + blk * 8192))[j] = make_uint4(0, 0, 0, 0);
    } else if (idx < Z_S0 + Z_S1) {
        int i = idx - Z_S0;
        int i512 = i >> 9, j = i & 511;
        int b = i512 >> 2, q = i512 & 3;
        int kc = (q < 2) ? 2 + q : 6 + (q - 2);
        int hh = (q < 2) ? 127 : 0;
        size_t blk = ((size_t)(b * 128 + hh) * 8 + kc);
        ((uint4*)((char*)g_ys + blk * 8192))[j] = make_uint4(0, 0, 0, 0);
    } else {
        int i = idx - Z_S0 - Z_S1;
        if (i >= Z_S2) return;
        int sel = i >> 17, r = i & 131071;
        int b = r >> 13, r2 = r & 8191;
        int hh = r2 >> 6, r3 = r2 & 63;
        int kc2 = r3 >> 5, kk = r3 & 31;
        int kc, wp;
        if (sel == 0) { kc = kc2;     wp = 0;   }
        else          { kc = 4 + kc2; wp = 127; }
        size_t blk = ((size_t)(b * 128 + hh) * 8 + kc);
        *(__half*)((char*)g_ys + blk * 8192 + ysoff(kk, wp)) = __float2half_rn(0.f);
    }
}

// ----------------------------------------------------------------- MMA -----
struct FragAddr { uint a[4]; uint b[8]; };

__device__ __forceinline__ void frag_init(FragAddr& fa, uint smb, int wm, int wn,
                                          int lane) {
    const int j = lane >> 3, r = lane & 7;
    const int jk = (j & 1) << 3, jn = j >> 1;
#pragma unroll
    for (int ks = 0; ks < 2; ++ks) {
#pragma unroll
        for (int mf = 0; mf < 2; ++mf)
            fa.a[ks * 2 + mf] = smb + (((ks * 8 + wm * 2 + mf) * 32 + lane) << 4);
#pragma unroll
        for (int p = 0; p < 4; ++p) {
            int krow = ks * 16 + jk + r;
            int oct  = wn * 8 + 2 * p + jn;
            fa.b[ks * 4 + p] = smb + A_BYTES + krow * 256
                             + ((uint)(oct ^ (krow & 7)) << 4);
        }
    }
}

__device__ __forceinline__ void mma_chunk(const FragAddr& fa, int soff,
                                          float acc[2][8][4]) {
#pragma unroll
    for (int ks = 0; ks < 2; ++ks) {
        uint4 a[2];
#pragma unroll
        for (int mf = 0; mf < 2; ++mf)
            asm volatile("ld.shared.v4.b32 {%0,%1,%2,%3}, [%4];"
                : "=r"(a[mf].x), "=r"(a[mf].y), "=r"(a[mf].z), "=r"(a[mf].w)
                : "r"(fa.a[ks * 2 + mf] + soff));
        uint bf[8][2];
#pragma unroll
        for (int p = 0; p < 4; ++p) {
            uint d0, d1, d2, d3;
            asm volatile("ldmatrix.sync.aligned.m8n8.x4.trans.shared.b16 "
                "{%0,%1,%2,%3}, [%4];"
                : "=r"(d0), "=r"(d1), "=r"(d2), "=r"(d3)
                : "r"(fa.b[ks * 4 + p] + soff));
            bf[2 * p][0] = d0; bf[2 * p][1] = d1;
            bf[2 * p + 1][0] = d2; bf[2 * p + 1][1] = d3;
        }
#pragma unroll
        for (int mf = 0; mf < 2; ++mf)
#pragma unroll
            for (int nf = 0; nf < 8; ++nf)
                MMA16(acc[mf][nf], a[mf], bf[nf][0], bf[nf][1]);
    }
}

// ------------------------------------------------------ conv3x3 + BN + SiLU
__global__ __launch_bounds__(NTHR, 2) void k_conv3(
    const float* __restrict__ gamma, const float* __restrict__ beta,
    const float* __restrict__ mean,  const float* __restrict__ var)
{
    extern __shared__ __align__(16) char dsm[];
    __shared__ __align__(8) unsigned long long s_full[NSTG], s_empty[NSTG];
    const uint smb = smem_u32(dsm);
    const uint fullb = smem_u32(&s_full[0]);
    const uint emptyb = smem_u32(&s_empty[0]);

    const int tid = threadIdx.x;
    const int wrp = tid >> 5, lane = tid & 31;
    const int wm = wrp >> 1, wn = wrp & 1;
    const int h0  = blockIdx.x;
    const int ocg = blockIdx.y, oc0 = ocg * 128;
    const int b   = blockIdx.z;

    if (tid < NSTG) { MBAR_INIT(fullb + tid * 8, 1); MBAR_INIT(emptyb + tid * 8, 8); }
    __syncthreads();

    FragAddr fa;
    frag_init(fa, smb, wm, wn, lane);

    float acc[2][8][4];
#pragma unroll
    for (int i = 0; i < 2; ++i)
#pragma unroll
        for (int jj = 0; jj < 8; ++jj)
#pragma unroll
            for (int qq = 0; qq < 4; ++qq) acc[i][jj][qq] = 0.0f;

#define ISSUE_CONV(nit, s) do { \
        int kc_ = (nit) / 9, tap_ = (nit) - 9 * kc_; \
        int ky_ = tap_ / 3, kx_ = tap_ - 3 * ky_; \
        uint mbx = fullb + (s) * 8; \
        MBAR_EXPECT(mbx, 16384u); \
        BULK_G2S(smb + (s) * STAGE, \
                 (const char*)g_wA16 + (size_t)((nit) * 2 + ocg) * 8192, 8192u, mbx); \
        size_t blk_ = ((size_t)(kx_ * B_ + b) * 130 + (h0 + ky_)) * 4 + kc_; \
        BULK_G2S(smb + (s) * STAGE + A_BYTES, \
                 (const char*)g_xs + blk_ * 8192, 8192u, mbx); \
    } while (0)

    if (tid == 0) { ISSUE_CONV(0, 0); ISSUE_CONV(1, 1); ISSUE_CONV(2, 2); }

#pragma unroll 1
    for (int blk = 0; blk < 9; ++blk) {
        const uint ph = (uint)(blk & 1);
#pragma unroll
        for (int q = 0; q < 4; ++q) {
            const int it = blk * 4 + q;
            mbar_wait(fullb + q * 8, ph);
            mma_chunk(fa, q * STAGE, acc);
            if (lane == 0) MBAR_ARRIVE(emptyb + q * 8);
            if (tid == 0) {
                const int nx = it + 3;
                if (nx < 36) {
                    const int sn = (q + 3) & 3;
                    const int un = blk + (q >= 1 ? 1 : 0);
                    if (un >= 1) mbar_wait(emptyb + sn * 8, (uint)((un - 1) & 1));
                    ISSUE_CONV(nx, sn);
                }
            }
        }
    }
#undef ISSUE_CONV

    // ---- epilogue phase 1: BN+SiLU -> smem tiles (yi plain, ysh w-shifted) --
    __syncthreads();
    char* yiS = dsm;                 // [128][136] half
    char* ysS = dsm + 128 * YROW;    // [128][136] half
    const int kcg = (oc0 >> 5) + wm;
    const int grp = (kcg >> 1) & 3;
    const int h = h0;
#pragma unroll
    for (int mf = 0; mf < 2; ++mf) {
        const int kk_a = mf * 16 + (lane >> 2), kk_b = kk_a + 8;
        const int ol_a = wm * 32 + kk_a, ol_b = ol_a + 8;
        const int oc_a = oc0 + ol_a, oc_b = oc_a + 8;
        const float inva = __ldg(&gamma[oc_a]) * rsqrtf(__ldg(&var[oc_a]) + EPSBN);
        const float bba  = __ldg(&beta[oc_a]) - __ldg(&mean[oc_a]) * inva;
        const float invb = __ldg(&gamma[oc_b]) * rsqrtf(__ldg(&var[oc_b]) + EPSBN);
        const float bbb  = __ldg(&beta[oc_b]) - __ldg(&mean[oc_b]) * invb;
#pragma unroll
        for (int nf = 0; nf < 8; ++nf) {
            const int w = wn * 64 + nf * 8 + (lane & 3) * 2;
            __half2 uh = __floats2half2_rn(silu_f(acc[mf][nf][0] * inva + bba),
                                           silu_f(acc[mf][nf][1] * inva + bba));
            __half2 vh = __floats2half2_rn(silu_f(acc[mf][nf][2] * invb + bbb),
                                           silu_f(acc[mf][nf][3] * invb + bbb));
            *(__half2*)(yiS + ol_a * YROW + w * 2) = uh;
            *(__half2*)(yiS + ol_b * YROW + w * 2) = vh;
            if (grp == 0) {            // z[j] = y[j-1]
                *(__half*)(ysS + ol_a * YROW + (w + 1) * 2) = __low2half(uh);
                *(__half*)(ysS + ol_b * YROW + (w + 1) * 2) = __low2half(vh);
                if (w < 126) {
                    *(__half*)(ysS + ol_a * YROW + (w + 2) * 2) = __high2half(uh);
                    *(__half*)(ysS + ol_b * YROW + (w + 2) * 2) = __high2half(vh);
                }
                if (w == 0) {
                    *(__half*)(ysS + ol_a * YROW) = __float2half_rn(0.f);
                    *(__half*)(ysS + ol_b * YROW) = __float2half_rn(0.f);
                }
            } else if (grp == 2) {     // z[j] = y[j+1]
                if (w > 0) {
                    *(__half*)(ysS + ol_a * YROW + (w - 1) * 2) = __low2half(uh);
                    *(__half*)(ysS + ol_b * YROW + (w - 1) * 2) = __low2half(vh);
                }
                *(__half*)(ysS + ol_a * YROW + w * 2) = __high2half(uh);
                *(__half*)(ysS + ol_b * YROW + w * 2) = __high2half(vh);
                if (w == 126) {
                    *(__half*)(ysS + ol_a * YROW + 127 * 2) = __float2half_rn(0.f);
                    *(__half*)(ysS + ol_b * YROW + 127 * 2) = __float2half_rn(0.f);
                }
            } else {                   // row-shifted groups: plain copy
                *(__half2*)(ysS + ol_a * YROW + w * 2) = uh;
                *(__half2*)(ysS + ol_b * YROW + w * 2) = vh;
            }
        }
    }
    __syncthreads();

    // ---- epilogue phase 2: coalesced STG -----------------------------------
    const int tg = tid & 15, tr = tid >> 4;
#pragma unroll
    for (int r = 0; r < 8; ++r) {
        const int ol = r * 16 + tr;
        const int goc = oc0 + ol;
        uint4 vi = *(uint4*)(yiS + ol * YROW + tg * 16);
        *(uint4*)((char*)g_yi + (((size_t)b * C2 + goc) * HW + (size_t)h * W_ + tg * 8) * 2) = vi;
        const int grp_r = (goc >> 6) & 3;
        const int hd = h + (grp_r == 1 ? -1 : (grp_r == 3 ? 1 : 0));
        if ((uint)hd < 128u) {
            const int kcb = goc >> 5, kk = ol & 31;
            uint4 vs = *(uint4*)(ysS + ol * YROW + tg * 16);
            char* dst = (char*)g_ys + (((size_t)(b * 128 + hd) * 8 + kcb) * 8192)
                      + kk * 256 + ((uint)(tg ^ (kk & 7)) << 4);
            *(uint4*)dst = vs;
        }
    }
}

// --------------------------- conv1x1(shifted y) + bias + BN + id + SiLU ----
__global__ __launch_bounds__(NTHR, 2) void k_pw(
    const float* __restrict__ b1,
    const float* __restrict__ gamma, const float* __restrict__ beta,
    const float* __restrict__ mean,  const float* __restrict__ var,
    float* __restrict__ out)
{
    extern __shared__ __align__(16) char dsm[];
    __shared__ __align__(8) unsigned long long s_full[NSTG], s_empty[NSTG];
    const uint smb = smem_u32(dsm);
    const uint fullb = smem_u32(&s_full[0]);
    const uint emptyb = smem_u32(&s_empty[0]);

    const int tid = threadIdx.x;
    const int wrp = tid >> 5, lane = tid & 31;
    const int wm = wrp >> 1, wn = wrp & 1;
    const int h0  = blockIdx.x;
    const int ocg = blockIdx.y, oc0 = ocg * 128;
    const int b   = blockIdx.z;

    if (tid < NSTG) { MBAR_INIT(fullb + tid * 8, 1); MBAR_INIT(emptyb + tid * 8, 8); }
    __syncthreads();

    FragAddr fa;
    frag_init(fa, smb, wm, wn, lane);

    float acc[2][8][4];
#pragma unroll
    for (int i = 0; i < 2; ++i)
#pragma unroll
        for (int jj = 0; jj < 8; ++jj)
#pragma unroll
            for (int qq = 0; qq < 4; ++qq) acc[i][jj][qq] = 0.0f;

#define ISSUE_PW(nit, s) do { \
        uint mbx = fullb + (s) * 8; \
        MBAR_EXPECT(mbx, 16384u); \
        BULK_G2S(smb + (s) * STAGE, \
                 (const char*)g_wB16 + (size_t)((nit) * 2 + ocg) * 8192, 8192u, mbx); \
        size_t blk_ = ((size_t)(b * 128 + h0) * 8 + (nit)); \
        BULK_G2S(smb + (s) * STAGE + A_BYTES, \
                 (const char*)g_ys + blk_ * 8192, 8192u, mbx); \
    } while (0)

    if (tid == 0) { ISSUE_PW(0, 0); ISSUE_PW(1, 1); ISSUE_PW(2, 2); }

#pragma unroll 1
    for (int blk = 0; blk < 2; ++blk) {
        const uint ph = (uint)(blk & 1);
#pragma unroll
        for (int q = 0; q < 4; ++q) {
            const int it = blk * 4 + q;
            mbar_wait(fullb + q * 8, ph);
            mma_chunk(fa, q * STAGE, acc);
            if (lane == 0) MBAR_ARRIVE(emptyb + q * 8);
            if (tid == 0) {
                const int nx = it + 3;
                if (nx < 8) {
                    const int sn = (q + 3) & 3;
                    const int un = blk + (q >= 1 ? 1 : 0);
                    if (un >= 1) mbar_wait(emptyb + sn * 8, (uint)((un - 1) & 1));
                    ISSUE_PW(nx, sn);
                }
            }
        }
    }
#undef ISSUE_PW

    // ---- epilogue phase 1: (acc + bias)*BN -> smem z tile (fp32) -----------
    __syncthreads();
    char* zS = dsm;    // [128][136] float
    const int h = h0;
#pragma unroll
    for (int mf = 0; mf < 2; ++mf) {
        const int ol_a = wm * 32 + mf * 16 + (lane >> 2), ol_b = ol_a + 8;
        const int oc_a = oc0 + ol_a, oc_b = oc_a + 8;
        const float inva = __ldg(&gamma[oc_a]) * rsqrtf(__ldg(&var[oc_a]) + EPSBN);
        const float bba  = __ldg(&beta[oc_a]) - __ldg(&mean[oc_a]) * inva;
        const float bsa  = __ldg(&b1[oc_a]);
        const float invb = __ldg(&gamma[oc_b]) * rsqrtf(__ldg(&var[oc_b]) + EPSBN);
        const float bbb  = __ldg(&beta[oc_b]) - __ldg(&mean[oc_b]) * invb;
        const float bsb  = __ldg(&b1[oc_b]);
#pragma unroll
        for (int nf = 0; nf < 8; ++nf) {
            const int w = wn * 64 + nf * 8 + (lane & 3) * 2;
            float2 u, v;
            u.x = (acc[mf][nf][0] + bsa) * inva + bba;
            u.y = (acc[mf][nf][1] + bsa) * inva + bba;
            v.x = (acc[mf][nf][2] + bsb) * invb + bbb;
            v.y = (acc[mf][nf][3] + bsb) * invb + bbb;
            *(float2*)(zS + ol_a * ZROW + w * 4) = u;
            *(float2*)(zS + ol_b * ZROW + w * 4) = v;
        }
    }
    __syncthreads();

    // ---- epilogue phase 2: +identity, SiLU, coalesced out ------------------
    const int tg = tid & 15, tr = tid >> 4;
#pragma unroll
    for (int r = 0; r < 8; ++r) {
        const int ol = r * 16 + tr;
        const int goc = oc0 + ol;
        float4 z0 = *(float4*)(zS + ol * ZROW + tg * 32);
        float4 z1 = *(float4*)(zS + ol * ZROW + tg * 32 + 16);
        const size_t goff = ((size_t)b * C2 + goc) * HW + (size_t)h * W_ + tg * 8;
        uint4 idv = *(const uint4*)((const char*)g_yi + goff * 2);
        float2 i0 = __half22float2(*(__half2*)&idv.x);
        float2 i1 = __half22float2(*(__half2*)&idv.y);
        float2 i2 = __half22float2(*(__half2*)&idv.z);
        float2 i3 = __half22float2(*(__half2*)&idv.w);
        float4 o0, o1;
        o0.x = silu_f(z0.x + i0.x); o0.y = silu_f(z0.y + i0.y);
        o0.z = silu_f(z0.z + i1.x); o0.w = silu_f(z0.w + i1.y);
        o1.x = silu_f(z1.x + i2.x); o1.y = silu_f(z1.y + i2.y);
        o1.z = silu_f(z1.z + i3.x); o1.w = silu_f(z1.w + i3.y);
        *(float4*)(out + goff)     = o0;
        *(float4*)(out + goff + 4) = o1;
    }
}

// ---------------------------------------------------------------------------
extern "C" void kernel_launch(void* const* d_in, const int* in_sizes, int n_in,
                              void* d_out, int out_size)
{
    const float* x     = (const float*)d_in[0];
    const float* wconv = (const float*)d_in[1];
    const float* w1    = (const float*)d_in[2];
    const float* b1    = (const float*)d_in[3];
    const float* gamma = (const float*)d_in[4];
    const float* beta  = (const float*)d_in[5];
    const float* mean  = (const float*)d_in[6];
    const float* var   = (const float*)d_in[7];
    float* out = (float*)d_out;

    static bool attr_done = false;
    if (!attr_done) {
        cudaFuncSetAttribute(k_conv3, cudaFuncAttributeMaxDynamicSharedMemorySize, DSMEM_BYTES);
        cudaFuncSetAttribute(k_pw,    cudaFuncAttributeMaxDynamicSharedMemorySize, DSMEM_BYTES);
        attr_done = true;
    }

    k_repack<<<(C2 * C1 * 9 + C2 * C2 + 255) / 256, 256>>>(wconv, w1);
    k_prep_x<<<dim3(H_, B_), 256>>>(x);
    k_zero  <<<(Z_S0 + Z_S1 + Z_S2 + 255) / 256, 256>>>();

    dim3 grid(H_, 2, B_);
    k_conv3<<<grid, NTHR, DSMEM_BYTES>>>(gamma, beta, mean, var);
    k_pw   <<<grid, NTHR, DSMEM_BYTES>>>(b1, gamma, beta, mean, var, out);
}

// round 17
// speedup vs baseline: 1.0777x; 1.0777x over previous
#include <cuda_runtime.h>
#include <cuda_fp16.h>

// SConv R16: R14 (best: 626.6us) + distributed producer — ring stage s is
// issued by warp s's lane 0 instead of a single thread-0 producer.
// CTA: 256 thr (8 warps 4Mx2N, warp 32x64), tile 128oc x 128px, 2 CTAs/SM.

#define B_  16
#define C1  128
#define C2  256
#define H_  128
#define W_  128
#define HW  (H_*W_)
#define EPSBN 1e-5f

typedef unsigned int uint;

__device__ __half g_xs[(size_t)3 * B_ * 130 * 4 * 4096];
__device__ __half g_ys[(size_t)B_ * 128 * 8 * 4096];
__device__ __half g_yi [(size_t)B_ * C2 * HW];
__device__ __half g_wA16[36 * 2 * 4096];
__device__ __half g_wB16[ 8 * 2 * 4096];

__device__ __forceinline__ float silu_f(float v) { return v / (1.0f + __expf(-v)); }
__device__ __forceinline__ uint smem_u32(const void* p) {
    uint a;
    asm("{ .reg .u64 t; cvta.to.shared.u64 t, %1; cvt.u32.u64 %0, t; }" : "=r"(a) : "l"(p));
    return a;
}

#define MMA16(d, a, b0v, b1v) \
    asm volatile("mma.sync.aligned.m16n8k16.row.col.f32.f16.f16.f32 " \
        "{%0,%1,%2,%3}, {%4,%5,%6,%7}, {%8,%9}, {%0,%1,%2,%3};" \
        : "+f"((d)[0]), "+f"((d)[1]), "+f"((d)[2]), "+f"((d)[3]) \
        : "r"((a).x), "r"((a).y), "r"((a).z), "r"((a).w), "r"(b0v), "r"(b1v))

#define MBAR_INIT(a, c) \
    asm volatile("mbarrier.init.shared.b64 [%0], %1;" :: "r"(a), "r"(c) : "memory")
#define MBAR_EXPECT(a, by) \
    asm volatile("mbarrier.arrive.expect_tx.shared.b64 _, [%0], %1;" :: "r"(a), "r"(by) : "memory")
#define MBAR_ARRIVE(a) \
    asm volatile("mbarrier.arrive.shared.b64 _, [%0];" :: "r"(a) : "memory")
#define BULK_G2S(dst, src, sz, mb) \
    asm volatile("cp.async.bulk.shared::cta.global.mbarrier::complete_tx::bytes [%0], [%1], %2, [%3];" \
        :: "r"(dst), "l"(src), "r"(sz), "r"(mb) : "memory")
__device__ __forceinline__ void mbar_wait(uint a, uint ph) {
    asm volatile(
        "{\n\t.reg .pred P;\n\tWL%=:\n\t"
        "mbarrier.try_wait.parity.shared.b64 P, [%0], %1;\n\t"
        "@!P bra WL%=;\n\t}" :: "r"(a), "r"(ph) : "memory");
}

#define A_BYTES 8192
#define B_BYTES 8192
#define STAGE   (A_BYTES + B_BYTES)
#define NSTG    4
#define DSMEM_BYTES (NSTG * STAGE)    // 65536 per CTA, 2 CTAs/SM
#define NTHR 256

__device__ __forceinline__ int ysoff(int kk, int wp) {
    return kk * 256 + ((((wp >> 3) ^ (kk & 7))) << 4) + (wp & 7) * 2;
}

// --------------------------------------------------------- prep kernels ----
__device__ __forceinline__ int fragoff(int m, int kk) {
    return (((kk >> 4) * 8 + (m >> 4)) * 32 + (((m & 7) << 2) | ((kk >> 1) & 3))) * 8
         + (((kk >> 3) & 1) * 2 + ((m >> 3) & 1)) * 2 + (kk & 1);
}
__global__ __launch_bounds__(256) void k_repack(const float* __restrict__ wc,
                                                const float* __restrict__ w1) {
    int idx = blockIdx.x * 256 + threadIdx.x;
    if (idx < C2 * C1 * 9) {
        int tap = idx % 9, rest = idx / 9;
        int ic = rest % C1, oc = rest / C1;
        int it = (ic >> 5) * 9 + tap;
        g_wA16[(size_t)(it * 2 + (oc >> 7)) * 4096 + fragoff(oc & 127, ic & 31)] =
            __float2half_rn(wc[idx]);
    } else {
        int j = idx - C2 * C1 * 9;
        if (j >= C2 * C2) return;
        int ic = j % C2, oc = j / C2;
        g_wB16[(size_t)((ic >> 5) * 2 + (oc >> 7)) * 4096 + fragoff(oc & 127, ic & 31)] =
            __float2half_rn(w1[j]);
    }
}

__global__ __launch_bounds__(256) void k_prep_x(const float* __restrict__ x) {
    const int h = blockIdx.x, b = blockIdx.y;
    const int tid = threadIdx.x;
#pragma unroll
    for (int i = 0; i < 8; ++i) {
        int item = tid + i * 256;
        int kc = item >> 9, r = item & 511;
        int kk = r >> 4, g = r & 15;
        const float* src = x + (((size_t)(b * C1 + kc * 32 + kk)) * H_ + h) * W_;
        int w0 = g * 8;
        float v[10];
#pragma unroll
        for (int j = 0; j < 10; ++j) {
            int gw = w0 - 1 + j;
            v[j] = ((uint)gw < 128u) ? __ldg(src + gw) : 0.f;
        }
        uint off = (uint)(kk * 256 + ((g ^ (kk & 7)) << 4));
#pragma unroll
        for (int kx = 0; kx < 3; ++kx) {
            __align__(16) __half hh[8];
#pragma unroll
            for (int j = 0; j < 8; ++j) hh[j] = __float2half_rn(v[j + kx]);
            size_t blk = ((size_t)(kx * B_ + b) * 130 + (h + 1)) * 4 + kc;
            *(uint4*)((char*)g_xs + blk * 8192 + off) = *(const uint4*)hh;
        }
    }
}

#define Z_S0 196608
#define Z_S1 32768
#define Z_S2 262144
__global__ __launch_bounds__(256) void k_zero() {
    int idx = blockIdx.x * 256 + threadIdx.x;
    if (idx < Z_S0) {
        int i512 = idx >> 9, j = idx & 511;
        int kx = i512 % 3, rest = i512 / 3;
        int b = rest % 16; rest /= 16;
        int e = rest % 2, kc = rest / 2;
        size_t blk = ((size_t)(kx * B_ + b) * 130 + (e ? 129 : 0)) * 4 + kc;
        ((uint4*)((char*)g_xs + blk * 8192))[j] = make_uint4(0, 0, 0, 0);
    } else if (idx < Z_S0 + Z_S1) {
        int i = idx - Z_S0;
        int i512 = i >> 9, j = i & 511;
        int b = i512 >> 2, q = i512 & 3;
        int kc = (q < 2) ? 2 + q : 6 + (q - 2);
        int hh = (q < 2) ? 127 : 0;
        size_t blk = ((size_t)(b * 128 + hh) * 8 + kc);
        ((uint4*)((char*)g_ys + blk * 8192))[j] = make_uint4(0, 0, 0, 0);
    } else {
        int i = idx - Z_S0 - Z_S1;
        if (i >= Z_S2) return;
        int sel = i >> 17, r = i & 131071;
        int b = r >> 13, r2 = r & 8191;
        int hh = r2 >> 6, r3 = r2 & 63;
        int kc2 = r3 >> 5, kk = r3 & 31;
        int kc, wp;
        if (sel == 0) { kc = kc2;     wp = 0;   }
        else          { kc = 4 + kc2; wp = 127; }
        size_t blk = ((size_t)(b * 128 + hh) * 8 + kc);
        *(__half*)((char*)g_ys + blk * 8192 + ysoff(kk, wp)) = __float2half_rn(0.f);
    }
}

// ----------------------------------------------------------------- MMA -----
struct FragAddr { uint a[4]; uint b[8]; };

__device__ __forceinline__ void frag_init(FragAddr& fa, uint smb, int wm, int wn,
                                          int lane) {
    const int j = lane >> 3, r = lane & 7;
    const int jk = (j & 1) << 3, jn = j >> 1;
#pragma unroll
    for (int ks = 0; ks < 2; ++ks) {
#pragma unroll
        for (int mf = 0; mf < 2; ++mf)
            fa.a[ks * 2 + mf] = smb + (((ks * 8 + wm * 2 + mf) * 32 + lane) << 4);
#pragma unroll
        for (int p = 0; p < 4; ++p) {
            int krow = ks * 16 + jk + r;
            int oct  = wn * 8 + 2 * p + jn;
            fa.b[ks * 4 + p] = smb + A_BYTES + krow * 256
                             + ((uint)(oct ^ (krow & 7)) << 4);
        }
    }
}

__device__ __forceinline__ void mma_chunk(const FragAddr& fa, int soff,
                                          float acc[2][8][4]) {
#pragma unroll
    for (int ks = 0; ks < 2; ++ks) {
        uint4 a[2];
#pragma unroll
        for (int mf = 0; mf < 2; ++mf)
            asm volatile("ld.shared.v4.b32 {%0,%1,%2,%3}, [%4];"
                : "=r"(a[mf].x), "=r"(a[mf].y), "=r"(a[mf].z), "=r"(a[mf].w)
                : "r"(fa.a[ks * 2 + mf] + soff));
        uint bf[8][2];
#pragma unroll
        for (int p = 0; p < 4; ++p) {
            uint d0, d1, d2, d3;
            asm volatile("ldmatrix.sync.aligned.m8n8.x4.trans.shared.b16 "
                "{%0,%1,%2,%3}, [%4];"
                : "=r"(d0), "=r"(d1), "=r"(d2), "=r"(d3)
                : "r"(fa.b[ks * 4 + p] + soff));
            bf[2 * p][0] = d0; bf[2 * p][1] = d1;
            bf[2 * p + 1][0] = d2; bf[2 * p + 1][1] = d3;
        }
#pragma unroll
        for (int mf = 0; mf < 2; ++mf)
#pragma unroll
            for (int nf = 0; nf < 8; ++nf)
                MMA16(acc[mf][nf], a[mf], bf[nf][0], bf[nf][1]);
    }
}

// ------------------------------------------------------ conv3x3 + BN + SiLU
__global__ __launch_bounds__(NTHR, 2) void k_conv3(
    const float* __restrict__ gamma, const float* __restrict__ beta,
    const float* __restrict__ mean,  const float* __restrict__ var)
{
    extern __shared__ __align__(16) char dsm[];
    __shared__ __align__(8) unsigned long long s_full[NSTG], s_empty[NSTG];
    const uint smb = smem_u32(dsm);
    const uint fullb = smem_u32(&s_full[0]);
    const uint emptyb = smem_u32(&s_empty[0]);

    const int tid = threadIdx.x;
    const int wrp = tid >> 5, lane = tid & 31;
    const int wm = wrp >> 1, wn = wrp & 1;
    const int h0  = blockIdx.x;
    const int ocg = blockIdx.y, oc0 = ocg * 128;
    const int b   = blockIdx.z;

    if (tid < NSTG) { MBAR_INIT(fullb + tid * 8, 1); MBAR_INIT(emptyb + tid * 8, 8); }
    __syncthreads();

    FragAddr fa;
    frag_init(fa, smb, wm, wn, lane);

    float acc[2][8][4];
#pragma unroll
    for (int i = 0; i < 2; ++i)
#pragma unroll
        for (int jj = 0; jj < 8; ++jj)
#pragma unroll
            for (int qq = 0; qq < 4; ++qq) acc[i][jj][qq] = 0.0f;

#define ISSUE_CONV(nit, s) do { \
        int kc_ = (nit) / 9, tap_ = (nit) - 9 * kc_; \
        int ky_ = tap_ / 3, kx_ = tap_ - 3 * ky_; \
        uint mbx = fullb + (s) * 8; \
        MBAR_EXPECT(mbx, 16384u); \
        BULK_G2S(smb + (s) * STAGE, \
                 (const char*)g_wA16 + (size_t)((nit) * 2 + ocg) * 8192, 8192u, mbx); \
        size_t blk_ = ((size_t)(kx_ * B_ + b) * 130 + (h0 + ky_)) * 4 + kc_; \
        BULK_G2S(smb + (s) * STAGE + A_BYTES, \
                 (const char*)g_xs + blk_ * 8192, 8192u, mbx); \
    } while (0)

    // prologue issues spread over warps 0..2 (lane 0)
    if (lane == 0) {
        if (wrp == 0) ISSUE_CONV(0, 0);
        else if (wrp == 1) ISSUE_CONV(1, 1);
        else if (wrp == 2) ISSUE_CONV(2, 2);
    }

#pragma unroll 1
    for (int blk = 0; blk < 9; ++blk) {
        const uint ph = (uint)(blk & 1);
#pragma unroll
        for (int q = 0; q < 4; ++q) {
            const int it = blk * 4 + q;
            mbar_wait(fullb + q * 8, ph);
            mma_chunk(fa, q * STAGE, acc);
            if (lane == 0) MBAR_ARRIVE(emptyb + q * 8);
            const int sn = (q + 3) & 3;          // compile-time per body
            if (wrp == sn && lane == 0) {        // distributed producer
                const int nx = it + 3;
                if (nx < 36) {
                    const int un = blk + (q >= 1 ? 1 : 0);
                    if (un >= 1) mbar_wait(emptyb + sn * 8, (uint)((un - 1) & 1));
                    ISSUE_CONV(nx, sn);
                }
            }
        }
    }
#undef ISSUE_CONV

    // epilogue: BN + SiLU -> g_yi (linear) + g_ys (shifted, swizzled tiles)
    const int kcg = (oc0 >> 5) + wm;
    const int grp = (kcg >> 1) & 3;
    const int h = h0;
#pragma unroll
    for (int mf = 0; mf < 2; ++mf) {
        const int kk_a = mf * 16 + (lane >> 2), kk_b = kk_a + 8;
        const int oc_a = kcg * 32 + kk_a, oc_b = oc_a + 8;
        const float inva = __ldg(&gamma[oc_a]) * rsqrtf(__ldg(&var[oc_a]) + EPSBN);
        const float bba  = __ldg(&beta[oc_a]) - __ldg(&mean[oc_a]) * inva;
        const float invb = __ldg(&gamma[oc_b]) * rsqrtf(__ldg(&var[oc_b]) + EPSBN);
        const float bbb  = __ldg(&beta[oc_b]) - __ldg(&mean[oc_b]) * invb;
        const size_t ra = ((size_t)b * C2 + oc_a) * HW;
        const size_t rb = ((size_t)b * C2 + oc_b) * HW;
#pragma unroll
        for (int nf = 0; nf < 8; ++nf) {
            const int w = wn * 64 + nf * 8 + (lane & 3) * 2;
            const int off = h * W_ + w;
            float2 u, v;
            u.x = silu_f(acc[mf][nf][0] * inva + bba);
            u.y = silu_f(acc[mf][nf][1] * inva + bba);
            v.x = silu_f(acc[mf][nf][2] * invb + bbb);
            v.y = silu_f(acc[mf][nf][3] * invb + bbb);
            __half2 uh = __floats2half2_rn(u.x, u.y);
            __half2 vh = __floats2half2_rn(v.x, v.y);
            *(__half2*)(g_yi + ra + off) = uh;
            *(__half2*)(g_yi + rb + off) = vh;
            if (grp == 1) {
                if (h > 0) {
                    char* ysb = (char*)g_ys + ((size_t)(b * 128 + h - 1) * 8 + kcg) * 8192;
                    *(__half2*)(ysb + ysoff(kk_a, w)) = uh;
                    *(__half2*)(ysb + ysoff(kk_b, w)) = vh;
                }
            } else if (grp == 3) {
                if (h < 127) {
                    char* ysb = (char*)g_ys + ((size_t)(b * 128 + h + 1) * 8 + kcg) * 8192;
                    *(__half2*)(ysb + ysoff(kk_a, w)) = uh;
                    *(__half2*)(ysb + ysoff(kk_b, w)) = vh;
                }
            } else if (grp == 0) {
                char* ysb = (char*)g_ys + ((size_t)(b * 128 + h) * 8 + kcg) * 8192;
                *(__half*)(ysb + ysoff(kk_a, w + 1)) = __low2half(uh);
                *(__half*)(ysb + ysoff(kk_b, w + 1)) = __low2half(vh);
                if (w < 126) {
                    *(__half*)(ysb + ysoff(kk_a, w + 2)) = __high2half(uh);
                    *(__half*)(ysb + ysoff(kk_b, w + 2)) = __high2half(vh);
                }
            } else {
                char* ysb = (char*)g_ys + ((size_t)(b * 128 + h) * 8 + kcg) * 8192;
                if (w > 0) {
                    *(__half*)(ysb + ysoff(kk_a, w - 1)) = __low2half(uh);
                    *(__half*)(ysb + ysoff(kk_b, w - 1)) = __low2half(vh);
                }
                *(__half*)(ysb + ysoff(kk_a, w)) = __high2half(uh);
                *(__half*)(ysb + ysoff(kk_b, w)) = __high2half(vh);
            }
        }
    }
}

// --------------------------- conv1x1(shifted y) + bias + BN + id + SiLU ----
__global__ __launch_bounds__(NTHR, 2) void k_pw(
    const float* __restrict__ b1,
    const float* __restrict__ gamma, const float* __restrict__ beta,
    const float* __restrict__ mean,  const float* __restrict__ var,
    float* __restrict__ out)
{
    extern __shared__ __align__(16) char dsm[];
    __shared__ __align__(8) unsigned long long s_full[NSTG], s_empty[NSTG];
    const uint smb = smem_u32(dsm);
    const uint fullb = smem_u32(&s_full[0]);
    const uint emptyb = smem_u32(&s_empty[0]);

    const int tid = threadIdx.x;
    const int wrp = tid >> 5, lane = tid & 31;
    const int wm = wrp >> 1, wn = wrp & 1;
    const int h0  = blockIdx.x;
    const int ocg = blockIdx.y, oc0 = ocg * 128;
    const int b   = blockIdx.z;

    if (tid < NSTG) { MBAR_INIT(fullb + tid * 8, 1); MBAR_INIT(emptyb + tid * 8, 8); }
    __syncthreads();

    FragAddr fa;
    frag_init(fa, smb, wm, wn, lane);

    float acc[2][8][4];
#pragma unroll
    for (int i = 0; i < 2; ++i)
#pragma unroll
        for (int jj = 0; jj < 8; ++jj)
#pragma unroll
            for (int qq = 0; qq < 4; ++qq) acc[i][jj][qq] = 0.0f;

#define ISSUE_PW(nit, s) do { \
        uint mbx = fullb + (s) * 8; \
        MBAR_EXPECT(mbx, 16384u); \
        BULK_G2S(smb + (s) * STAGE, \
                 (const char*)g_wB16 + (size_t)((nit) * 2 + ocg) * 8192, 8192u, mbx); \
        size_t blk_ = ((size_t)(b * 128 + h0) * 8 + (nit)); \
        BULK_G2S(smb + (s) * STAGE + A_BYTES, \
                 (const char*)g_ys + blk_ * 8192, 8192u, mbx); \
    } while (0)

    if (lane == 0) {
        if (wrp == 0) ISSUE_PW(0, 0);
        else if (wrp == 1) ISSUE_PW(1, 1);
        else if (wrp == 2) ISSUE_PW(2, 2);
    }

#pragma unroll 1
    for (int blk = 0; blk < 2; ++blk) {
        const uint ph = (uint)(blk & 1);
#pragma unroll
        for (int q = 0; q < 4; ++q) {
            const int it = blk * 4 + q;
            mbar_wait(fullb + q * 8, ph);
            mma_chunk(fa, q * STAGE, acc);
            if (lane == 0) MBAR_ARRIVE(emptyb + q * 8);
            const int sn = (q + 3) & 3;
            if (wrp == sn && lane == 0) {
                const int nx = it + 3;
                if (nx < 8) {
                    const int un = blk + (q >= 1 ? 1 : 0);
                    if (un >= 1) mbar_wait(emptyb + sn * 8, (uint)((un - 1) & 1));
                    ISSUE_PW(nx, sn);
                }
            }
        }
    }
#undef ISSUE_PW

    // epilogue: +bias, BN, +identity(fp16), SiLU -> out (fp32)
    const int h = h0;
#pragma unroll
    for (int mf = 0; mf < 2; ++mf) {
        const int oc_a = oc0 + wm * 32 + mf * 16 + (lane >> 2);
        const int oc_b = oc_a + 8;
        const float inva = __ldg(&gamma[oc_a]) * rsqrtf(__ldg(&var[oc_a]) + EPSBN);
        const float bba  = __ldg(&beta[oc_a]) - __ldg(&mean[oc_a]) * inva;
        const float bsa  = __ldg(&b1[oc_a]);
        const float invb = __ldg(&gamma[oc_b]) * rsqrtf(__ldg(&var[oc_b]) + EPSBN);
        const float bbb  = __ldg(&beta[oc_b]) - __ldg(&mean[oc_b]) * invb;
        const float bsb  = __ldg(&b1[oc_b]);
        const size_t ra = ((size_t)b * C2 + oc_a) * HW;
        const size_t rb = ((size_t)b * C2 + oc_b) * HW;
#pragma unroll
        for (int nf = 0; nf < 8; ++nf) {
            const int w = wn * 64 + nf * 8 + (lane & 3) * 2;
            const int off = h * W_ + w;
            float2 ida = __half22float2(*(const __half2*)(g_yi + ra + off));
            float2 idb = __half22float2(*(const __half2*)(g_yi + rb + off));
            float2 u, v; float z;
            z = (acc[mf][nf][0] + bsa) * inva + bba + ida.x; u.x = silu_f(z);
            z = (acc[mf][nf][1] + bsa) * inva + bba + ida.y; u.y = silu_f(z);
            z = (acc[mf][nf][2] + bsb) * invb + bbb + idb.x; v.x = silu_f(z);
            z = (acc[mf][nf][3] + bsb) * invb + bbb + idb.y; v.y = silu_f(z);
            *(float2*)(out + ra + off) = u;
            *(float2*)(out + rb + off) = v;
        }
    }
}

// ---------------------------------------------------------------------------
extern "C" void kernel_launch(void* const* d_in, const int* in_sizes, int n_in,
                              void* d_out, int out_size)
{
    const float* x     = (const float*)d_in[0];
    const float* wconv = (const float*)d_in[1];
    const float* w1    = (const float*)d_in[2];
    const float* b1    = (const float*)d_in[3];
    const float* gamma = (const float*)d_in[4];
    const float* beta  = (const float*)d_in[5];
    const float* mean  = (const float*)d_in[6];
    const float* var   = (const float*)d_in[7];
    float* out = (float*)d_out;

    static bool attr_done = false;
    if (!attr_done) {
        cudaFuncSetAttribute(k_conv3, cudaFuncAttributeMaxDynamicSharedMemorySize, DSMEM_BYTES);
        cudaFuncSetAttribute(k_pw,    cudaFuncAttributeMaxDynamicSharedMemorySize, DSMEM_BYTES);
        attr_done = true;
    }

    k_repack<<<(C2 * C1 * 9 + C2 * C2 + 255) / 256, 256>>>(wconv, w1);
    k_prep_x<<<dim3(H_, B_), 256>>>(x);
    k_zero  <<<(Z_S0 + Z_S1 + Z_S2 + 255) / 256, 256>>>();

    dim3 grid(H_, 2, B_);
    k_conv3<<<grid, NTHR, DSMEM_BYTES>>>(gamma, beta, mean, var);
    k_pw   <<<grid, NTHR, DSMEM_BYTES>>>(b1, gamma, beta, mean, var, out);
}